// round 5
// baseline (speedup 1.0000x reference)
#include <cuda_runtime.h>
#include <cuda_bf16.h>
#include <math.h>
#include <stdint.h>

// ---- problem constants ----
#define BB   4
#define MMOD 4
#define LL   1024
#define DMD  768
#define D2   384
#define LM   4096
#define DS   8
#define DTR  48
#define NXD  64
#define NC   64
#define CLN  64
#define ROWS (BB*LM)
#define CH   16                 // rows per inproj block

// ---- scratch ----
__device__ float g_xz   [ROWS*DMD];
__device__ float g_xc   [ROWS*D2];
__device__ float g_zc   [ROWS*D2];
__device__ float g_xdbl [ROWS*NXD];
__device__ float g_delta[ROWS*D2];
__device__ float g_y    [ROWS*D2];
__device__ float g_yg   [ROWS*D2];          // tf32-rounded gated output
__device__ float g_Wtf  [MMOD*DMD*D2];      // tf32-rounded out weights, [m][o][d]
__device__ float g_P    [BB*NC*DS*D2];
__device__ float g_HL   [BB*NC*DS*D2];
__device__ float g_INIT [BB*NC*DS*D2];

// =====================================================================
// tf32 helpers
// =====================================================================
__device__ __forceinline__ void tf32split(float x, float& h, float& l) {
    uint32_t u;
    asm("cvt.rna.tf32.f32 %0, %1;" : "=r"(u) : "f"(x));
    h = __uint_as_float(u);
    float r = x - h;
    asm("cvt.rna.tf32.f32 %0, %1;" : "=r"(u) : "f"(r));
    l = __uint_as_float(u);
}
#define MMA_TF32(c, a0, a1, a2, a3, b0, b1) \
    asm volatile("mma.sync.aligned.m16n8k8.row.col.f32.tf32.tf32.f32 " \
        "{%0,%1,%2,%3}, {%4,%5,%6,%7}, {%8,%9}, {%0,%1,%2,%3};" \
        : "+f"((c)[0]), "+f"((c)[1]), "+f"((c)[2]), "+f"((c)[3]) \
        : "r"(__float_as_uint(a0)), "r"(__float_as_uint(a1)), \
          "r"(__float_as_uint(a2)), "r"(__float_as_uint(a3)), \
          "r"(__float_as_uint(b0)), "r"(__float_as_uint(b1)))

__device__ __forceinline__ void cpa16(uint32_t dst, const void* src) {
    asm volatile("cp.async.cg.shared.global [%0], [%1], 16;" :: "r"(dst), "l"(src));
}

// =====================================================================
// Kernel 1: low-rank in-projection, weights staged in SMEM per 16-row block
// grid (LL/CH, MMOD, BB), 256 thr, dynamic smem = w1(48K)+w2T(48K)+row(3K)
// =====================================================================
#define IP_SMEM ((16*DMD + 4*DMD*4 + DMD)*4)

__global__ __launch_bounds__(256) void k_inproj2(
    const float* __restrict__ hs, const float* __restrict__ w1,
    const float* __restrict__ lng, const float* __restrict__ lnb,
    const float* __restrict__ w2, const int* __restrict__ midx)
{
    extern __shared__ float smem[];
    float*  sw1  = smem;                       // [16][768]
    float4* sw2v = (float4*)(smem + 16*DMD);   // [4][768] : sw2v[g][d] = w2[d][4g..4g+3]
    float*  sh   = smem + 16*DMD + 4*DMD*4;    // [768]
    __shared__ float st[16];
    __shared__ float s_mu, s_rstd;

    int l0 = blockIdx.x*CH, m = blockIdx.y, b = blockIdx.z;
    int tid = threadIdx.x;
    int wi = midx[m];

    // stage weights once
    const float4* w1p = (const float4*)(w1 + (size_t)wi*16*DMD);
    for (int i = tid; i < 16*DMD/4; i += 256) ((float4*)sw1)[i] = w1p[i];
    const float* w2p = w2 + (size_t)wi*DMD*16;
    for (int i = tid; i < DMD*4; i += 256) {
        int d = i >> 2, g = i & 3;
        sw2v[g*DMD + d] = *(const float4*)(w2p + d*16 + g*4);
    }
    __syncthreads();

    int w = tid >> 5, lane = tid & 31;
    for (int li = 0; li < CH; li++) {
        int l = l0 + li;
        const float4* hrow = (const float4*)(hs + ((size_t)(b*MMOD + m)*LL + l)*DMD);
        for (int i = tid; i < DMD/4; i += 256) ((float4*)sh)[i] = hrow[i];
        __syncthreads();

        // stage 1: 16 dots of length 768 (warp per 2 rows)
        #pragma unroll
        for (int q = 0; q < 2; q++) {
            int r = w*2 + q;
            const float* wrow = sw1 + r*DMD;
            float s = 0.f;
            #pragma unroll
            for (int d0 = lane*4; d0 < DMD; d0 += 128) {
                float4 h4 = *(const float4*)(sh + d0);
                float4 w4 = *(const float4*)(wrow + d0);
                s += h4.x*w4.x + h4.y*w4.y + h4.z*w4.z + h4.w*w4.w;
            }
            #pragma unroll
            for (int o = 16; o > 0; o >>= 1) s += __shfl_xor_sync(0xffffffffu, s, o);
            if (lane == 0) st[r] = s;
        }
        __syncthreads();
        if (tid == 0) {
            float mu = 0.f;
            #pragma unroll
            for (int r = 0; r < 16; r++) mu += st[r];
            mu *= (1.f/16.f);
            float var = 0.f;
            #pragma unroll
            for (int r = 0; r < 16; r++) { float d = st[r]-mu; var += d*d; }
            var *= (1.f/16.f);
            s_mu = mu; s_rstd = rsqrtf(var + 1e-5f);
        }
        __syncthreads();
        if (tid < 16) {
            float v = (st[tid]-s_mu)*s_rstd*lng[wi*16+tid] + lnb[wi*16+tid];
            st[tid] = 0.5f*v*(1.f + erff(v*0.70710678118654752f));
        }
        __syncthreads();

        float tr[16];
        #pragma unroll
        for (int r = 0; r < 16; r++) tr[r] = st[r];
        float* orow = g_xz + ((size_t)b*LM + (l*MMOD + m))*DMD;
        for (int d = tid; d < DMD; d += 256) {
            float s = 0.f;
            #pragma unroll
            for (int g = 0; g < 4; g++) {
                float4 wv = sw2v[g*DMD + d];
                s += tr[g*4+0]*wv.x + tr[g*4+1]*wv.y + tr[g*4+2]*wv.z + tr[g*4+3]*wv.w;
            }
            orow[d] = s;
        }
        __syncthreads();   // protect sh/st before next iter
    }
}

// =====================================================================
// Kernel 2: depthwise conv k=3 + SiLU on both halves
// =====================================================================
__global__ void k_conv(const float* __restrict__ wx, const float* __restrict__ wz)
{
    int idx = blockIdx.x*blockDim.x + threadIdx.x;
    if (idx >= ROWS*D2) return;
    int c = idx % D2;
    int row = idx / D2;
    int t = row & (LM-1);
    const float* base = g_xz + (size_t)row*DMD;

    float xm = (t > 0)      ? base[c - DMD] : 0.f;
    float x0 = base[c];
    float xp = (t < LM-1)   ? base[c + DMD] : 0.f;
    float vx = wx[c*3+0]*xm + wx[c*3+1]*x0 + wx[c*3+2]*xp;
    g_xc[idx] = vx / (1.f + __expf(-vx));

    float zm = (t > 0)      ? base[c+D2 - DMD] : 0.f;
    float z0 = base[c+D2];
    float zp = (t < LM-1)   ? base[c+D2 + DMD] : 0.f;
    float vz = wz[c*3+0]*zm + wz[c*3+1]*z0 + wz[c*3+2]*zp;
    g_zc[idx] = vz / (1.f + __expf(-vz));
}

// =====================================================================
// Tensor-core GEMM with tf32 hi/lo compensation (fp32-grade accuracy)
// C[r][n] = sum_k A[r][k]*B[n][k].  BM=BN=64, BK=16, 256 thr (4m x 2n warps).
// EPI=0: plain store;  EPI=1: softplus(acc + 2*bias[n])
// =====================================================================
#define GBKP 20
template<int EPI>
__global__ __launch_bounds__(256) void k_gemm_tc(
    const float* __restrict__ A, int lda, int K,
    const float* __restrict__ Bw, int ldb,
    float* __restrict__ C, int ldc,
    const float* __restrict__ bias)
{
    __shared__ float As[2][64*GBKP];
    __shared__ float Bs[2][64*GBKP];
    int tid = threadIdx.x, lane = tid & 31, wid = tid >> 5;
    int row0 = blockIdx.y*64, col0 = blockIdx.x*64;
    int warp_m = wid & 3, warp_n = wid >> 2;

    int lrow = tid >> 2, lk = (tid & 3)*4;
    const float* aptr = A  + (size_t)(row0 + lrow)*lda + lk;
    const float* bptr = Bw + (size_t)(col0 + lrow)*ldb + lk;
    uint32_t sAd = (uint32_t)__cvta_generic_to_shared(&As[0][0]) + (lrow*GBKP + lk)*4;
    uint32_t sBd = (uint32_t)__cvta_generic_to_shared(&Bs[0][0]) + (lrow*GBKP + lk)*4;
    const uint32_t BUF = 64*GBKP*4;

    float acc[4][4];
    #pragma unroll
    for (int i = 0; i < 4; i++)
        #pragma unroll
        for (int j = 0; j < 4; j++) acc[i][j] = 0.f;

    cpa16(sAd, aptr);
    cpa16(sBd, bptr);
    asm volatile("cp.async.commit_group;");

    int nk = K/16;
    for (int kt = 0; kt < nk; kt++) {
        asm volatile("cp.async.wait_group 0;");
        __syncthreads();
        if (kt + 1 < nk) {
            uint32_t bo = ((kt+1) & 1) * BUF;
            cpa16(sAd + bo, aptr + (kt+1)*16);
            cpa16(sBd + bo, bptr + (kt+1)*16);
            asm volatile("cp.async.commit_group;");
        }
        const float* a_s = &As[kt & 1][0];
        const float* b_s = &Bs[kt & 1][0];
        #pragma unroll
        for (int kh = 0; kh < 2; kh++) {
            int acol = kh*8 + (lane & 3);
            int r0 = warp_m*16 + (lane >> 2);
            float a0 = a_s[r0*GBKP + acol];
            float a1 = a_s[(r0+8)*GBKP + acol];
            float a2 = a_s[r0*GBKP + acol + 4];
            float a3 = a_s[(r0+8)*GBKP + acol + 4];
            float ah0, al0, ah1, al1, ah2, al2, ah3, al3;
            tf32split(a0, ah0, al0); tf32split(a1, ah1, al1);
            tf32split(a2, ah2, al2); tf32split(a3, ah3, al3);
            #pragma unroll
            for (int bn = 0; bn < 4; bn++) {
                int c0 = warp_n*32 + bn*8 + (lane >> 2);
                float b0 = b_s[c0*GBKP + acol];
                float b1 = b_s[c0*GBKP + acol + 4];
                float bh0, bl0, bh1, bl1;
                tf32split(b0, bh0, bl0); tf32split(b1, bh1, bl1);
                MMA_TF32(acc[bn], ah0, ah1, ah2, ah3, bh0, bh1);
                MMA_TF32(acc[bn], ah0, ah1, ah2, ah3, bl0, bl1);
                MMA_TF32(acc[bn], al0, al1, al2, al3, bh0, bh1);
            }
        }
    }

    #pragma unroll
    for (int bn = 0; bn < 4; bn++) {
        #pragma unroll
        for (int half = 0; half < 2; half++) {
            int r  = row0 + warp_m*16 + (lane >> 2) + half*8;
            int cc = col0 + warp_n*32 + bn*8 + (lane & 3)*2;
            float v0 = acc[bn][half*2 + 0];
            float v1 = acc[bn][half*2 + 1];
            if (EPI == 1) {
                v0 += 2.f*bias[cc];
                v1 += 2.f*bias[cc+1];
                v0 = (v0 > 20.f) ? v0 : log1pf(expf(v0));
                v1 = (v1 > 20.f) ? v1 : log1pf(expf(v1));
            }
            C[(size_t)r*ldc + cc]     = v0;
            C[(size_t)r*ldc + cc + 1] = v1;
        }
    }
}

// =====================================================================
// Scan phase A / B / C
// =====================================================================
__global__ __launch_bounds__(384) void k_scanA(const float* __restrict__ A_log)
{
    int c = blockIdx.x, b = blockIdx.y;
    int d = threadIdx.x;
    __shared__ float sB[CLN][8];
    for (int e = d; e < CLN*8; e += 384) {
        int j = e >> 3, s = e & 7;
        sB[j][s] = g_xdbl[((size_t)(b*LM + c*CLN + j))*NXD + 48 + s];
    }
    __syncthreads();
    float As[8];
    #pragma unroll
    for (int s = 0; s < 8; s++) As[s] = -__expf(A_log[d*8+s]);
    float h[8] = {}, P[8];
    #pragma unroll
    for (int s = 0; s < 8; s++) P[s] = 1.f;
    int rbase = b*LM + c*CLN;
    for (int j = 0; j < CLN; j++) {
        float dl = g_delta[(size_t)(rbase+j)*D2 + d];
        float xv = g_xc  [(size_t)(rbase+j)*D2 + d];
        float dx = dl*xv;
        #pragma unroll
        for (int s = 0; s < 8; s++) {
            float a = __expf(dl*As[s]);
            h[s] = a*h[s] + dx*sB[j][s];
            P[s] *= a;
        }
    }
    size_t o = ((size_t)(b*NC + c)*8)*D2 + d;
    #pragma unroll
    for (int s = 0; s < 8; s++) { g_P[o + (size_t)s*D2] = P[s]; g_HL[o + (size_t)s*D2] = h[s]; }
}

__global__ void k_scanB()
{
    int tid = blockIdx.x*blockDim.x + threadIdx.x;
    if (tid >= BB*D2*8) return;
    int d = tid % D2;
    int s = (tid / D2) & 7;
    int b = tid / (D2*8);
    float carry = 0.f;
    for (int c = 0; c < NC; c++) {
        size_t o = ((size_t)(b*NC + c)*8 + s)*D2 + d;
        g_INIT[o] = carry;
        carry = g_P[o]*carry + g_HL[o];
    }
}

__global__ __launch_bounds__(384) void k_scanC(const float* __restrict__ A_log,
                                               const float* __restrict__ Dw)
{
    int c = blockIdx.x, b = blockIdx.y;
    int d = threadIdx.x;
    __shared__ float sB[CLN][8];
    __shared__ float sC[CLN][8];
    for (int e = d; e < CLN*8; e += 384) {
        int j = e >> 3, s = e & 7;
        size_t rr = ((size_t)(b*LM + c*CLN + j))*NXD;
        sB[j][s] = g_xdbl[rr + 48 + s];
        sC[j][s] = g_xdbl[rr + 56 + s];
    }
    __syncthreads();
    float As[8];
    #pragma unroll
    for (int s = 0; s < 8; s++) As[s] = -__expf(A_log[d*8+s]);
    float h[8];
    size_t o = ((size_t)(b*NC + c)*8)*D2 + d;
    #pragma unroll
    for (int s = 0; s < 8; s++) h[s] = g_INIT[o + (size_t)s*D2];
    float Dv = Dw[d];
    int rbase = b*LM + c*CLN;
    for (int j = 0; j < CLN; j++) {
        float dl = g_delta[(size_t)(rbase+j)*D2 + d];
        float xv = g_xc  [(size_t)(rbase+j)*D2 + d];
        float dx = dl*xv;
        float y = Dv*xv;
        #pragma unroll
        for (int s = 0; s < 8; s++) {
            float a = __expf(dl*As[s]);
            h[s] = a*h[s] + dx*sB[j][s];
            y += h[s]*sC[j][s];
        }
        g_y[(size_t)(rbase+j)*D2 + d] = y;
    }
}

// =====================================================================
// Kernel 4: RMSNorm + gate; writes tf32-rounded fp32
// =====================================================================
__global__ __launch_bounds__(128) void k_rmsgate(const float* __restrict__ nw)
{
    int row = blockIdx.x;
    int tid = threadIdx.x;
    const float* yr = g_y  + (size_t)row*D2;
    const float* zr = g_zc + (size_t)row*D2;
    float v[3];
    float ss = 0.f;
    #pragma unroll
    for (int q = 0; q < 3; q++) { v[q] = yr[tid + q*128]; ss += v[q]*v[q]; }
    __shared__ float red[4];
    #pragma unroll
    for (int o = 16; o > 0; o >>= 1) ss += __shfl_xor_sync(0xffffffffu, ss, o);
    if ((tid & 31) == 0) red[tid >> 5] = ss;
    __syncthreads();
    float tot = red[0]+red[1]+red[2]+red[3];
    float rn = rsqrtf(tot*(1.f/384.f) + 1e-5f);
    float* og = g_yg + (size_t)row*D2;
    #pragma unroll
    for (int q = 0; q < 3; q++) {
        int dd = tid + q*128;
        float z = zr[dd];
        float sz = z/(1.f + __expf(-z));
        float val = v[q]*rn*nw[dd]*sz;
        uint32_t u;
        asm("cvt.rna.tf32.f32 %0, %1;" : "=r"(u) : "f"(val));
        og[dd] = __uint_as_float(u);
    }
}

// =====================================================================
// Kernel 4b: tf32-round out weights into [m][o][d]
// =====================================================================
__global__ __launch_bounds__(384) void k_prepW(const float* __restrict__ outw,
                                               const int* __restrict__ midx)
{
    int o = blockIdx.x, m = blockIdx.y;
    int d = threadIdx.x;
    int wi = midx[m];
    float w = outw[((size_t)wi*DMD + o)*D2 + d];
    uint32_t u;
    asm("cvt.rna.tf32.f32 %0, %1;" : "=r"(u) : "f"(w));
    g_Wtf[(size_t)(m*DMD + o)*D2 + d] = __uint_as_float(u);
}

// =====================================================================
// Kernel 5: out-projection via mma.sync tf32 (BM=128, BN=128, BK=16)
// grid = (DMD/128, (BB*LL)/128, MMOD)
// =====================================================================
#define BKP 20
#define NKIT 24

#define MMA_TF32_A(c, a, b) \
    asm volatile("mma.sync.aligned.m16n8k8.row.col.f32.tf32.tf32.f32 " \
        "{%0,%1,%2,%3}, {%4,%5,%6,%7}, {%8,%9}, {%0,%1,%2,%3};" \
        : "+f"((c)[0]), "+f"((c)[1]), "+f"((c)[2]), "+f"((c)[3]) \
        : "r"(__float_as_uint((a)[0])), "r"(__float_as_uint((a)[1])), \
          "r"(__float_as_uint((a)[2])), "r"(__float_as_uint((a)[3])), \
          "r"(__float_as_uint((b)[0])), "r"(__float_as_uint((b)[1])))

__global__ __launch_bounds__(256, 2) void k_outproj_mma(
    const float* __restrict__ scale_p, float* __restrict__ out)
{
    __shared__ float As[2][128*BKP];
    __shared__ float Bs[2][128*BKP];

    int tid = threadIdx.x, lane = tid & 31, wid = tid >> 5;
    int m  = blockIdx.z;
    int bx = blockIdx.x, by = blockIdx.y;
    int warp_m = wid & 1;
    int warp_n = wid >> 1;

    int lrow = tid >> 1;
    int lk0  = (tid & 1) * 8;
    int gr = by*128 + lrow;
    int bI = gr >> 10, lI = gr & 1023;
    const float* aptr = g_yg  + ((size_t)(bI*LM + lI*4 + m))*D2 + lk0;
    const float* bptr = g_Wtf + ((size_t)(m*DMD) + bx*128 + lrow)*D2 + lk0;
    uint32_t sAd = (uint32_t)__cvta_generic_to_shared(&As[0][0]) + (lrow*BKP + lk0)*4;
    uint32_t sBd = (uint32_t)__cvta_generic_to_shared(&Bs[0][0]) + (lrow*BKP + lk0)*4;
    const uint32_t BUFB = 128*BKP*4;

    float acc[4][4][4];
    #pragma unroll
    for (int i = 0; i < 4; i++)
        #pragma unroll
        for (int j = 0; j < 4; j++)
            #pragma unroll
            for (int q = 0; q < 4; q++) acc[i][j][q] = 0.f;

    cpa16(sAd,      aptr);
    cpa16(sAd + 16, aptr + 4);
    cpa16(sBd,      bptr);
    cpa16(sBd + 16, bptr + 4);
    asm volatile("cp.async.commit_group;");

    for (int kt = 0; kt < NKIT; kt++) {
        asm volatile("cp.async.wait_group 0;");
        __syncthreads();
        if (kt + 1 < NKIT) {
            uint32_t bo = ((kt+1) & 1) * BUFB;
            const float* ap = aptr + (kt+1)*16;
            const float* bp = bptr + (kt+1)*16;
            cpa16(sAd + bo,      ap);
            cpa16(sAd + bo + 16, ap + 4);
            cpa16(sBd + bo,      bp);
            cpa16(sBd + bo + 16, bp + 4);
            asm volatile("cp.async.commit_group;");
        }
        const float* a_s = &As[kt & 1][0];
        const float* b_s = &Bs[kt & 1][0];
        #pragma unroll
        for (int s = 0; s < 2; s++) {
            int acol = s*8 + (lane & 3);
            float ar[4][4];
            #pragma unroll
            for (int am = 0; am < 4; am++) {
                int r0 = warp_m*64 + am*16 + (lane >> 2);
                ar[am][0] = a_s[r0*BKP + acol];
                ar[am][1] = a_s[(r0+8)*BKP + acol];
                ar[am][2] = a_s[r0*BKP + acol + 4];
                ar[am][3] = a_s[(r0+8)*BKP + acol + 4];
            }
            float br[4][2];
            #pragma unroll
            for (int an = 0; an < 4; an++) {
                int c0 = warp_n*32 + an*8 + (lane >> 2);
                br[an][0] = b_s[c0*BKP + acol];
                br[an][1] = b_s[c0*BKP + acol + 4];
            }
            #pragma unroll
            for (int am = 0; am < 4; am++)
                #pragma unroll
                for (int an = 0; an < 4; an++)
                    MMA_TF32_A(acc[am][an], ar[am], br[an]);
        }
    }

    float sc = *scale_p;
    int r_base = by*128 + warp_m*64;
    int c_base = bx*128 + warp_n*32;
    #pragma unroll
    for (int am = 0; am < 4; am++) {
        #pragma unroll
        for (int half = 0; half < 2; half++) {
            int row = r_base + am*16 + (lane >> 2) + half*8;
            int ob = row >> 10, ol = row & 1023;
            float* orow = out + ((size_t)((ob*MMOD + m)*LL + ol))*DMD;
            #pragma unroll
            for (int an = 0; an < 4; an++) {
                int cc = c_base + an*8 + (lane & 3)*2;
                float2 v;
                v.x = acc[am][an][half*2 + 0] * sc;
                v.y = acc[am][an][half*2 + 1] * sc;
                *(float2*)(orow + cc) = v;
            }
        }
    }
}

// =====================================================================
extern "C" void kernel_launch(void* const* d_in, const int* in_sizes, int n_in,
                              void* d_out, int out_size)
{
    const float* hs   = (const float*)d_in[0];
    const float* w1   = (const float*)d_in[1];
    const float* lng  = (const float*)d_in[2];
    const float* lnb  = (const float*)d_in[3];
    const float* w2   = (const float*)d_in[4];
    const float* xpw  = (const float*)d_in[5];
    const float* dtw  = (const float*)d_in[6];
    const float* dtb  = (const float*)d_in[7];
    const float* alog = (const float*)d_in[8];
    const float* Dp   = (const float*)d_in[9];
    const float* cwx  = (const float*)d_in[10];
    const float* cwz  = (const float*)d_in[11];
    const float* nw   = (const float*)d_in[12];
    const float* outw = (const float*)d_in[13];
    const float* scl  = (const float*)d_in[14];
    const int*   midx = (const int*)d_in[15];
    float* out = (float*)d_out;

    float *p_xc, *p_xdbl, *p_delta;
    cudaGetSymbolAddress((void**)&p_xc,    g_xc);
    cudaGetSymbolAddress((void**)&p_xdbl,  g_xdbl);
    cudaGetSymbolAddress((void**)&p_delta, g_delta);

    cudaFuncSetAttribute(k_inproj2, cudaFuncAttributeMaxDynamicSharedMemorySize, IP_SMEM);

    k_inproj2<<<dim3(LL/CH, MMOD, BB), 256, IP_SMEM>>>(hs, w1, lng, lnb, w2, midx);
    k_conv<<<(ROWS*D2 + 255)/256, 256>>>(cwx, cwz);
    k_prepW<<<dim3(DMD, MMOD), 384>>>(outw, midx);
    k_gemm_tc<0><<<dim3(1, ROWS/64), 256>>>(p_xc, D2, D2, xpw, D2, p_xdbl, NXD, nullptr);
    k_gemm_tc<1><<<dim3(D2/64, ROWS/64), 256>>>(p_xdbl, NXD, DTR, dtw, DTR, p_delta, D2, dtb);
    k_scanA<<<dim3(NC, BB), 384>>>(alog);
    k_scanB<<<(BB*D2*8 + 255)/256, 256>>>();
    k_scanC<<<dim3(NC, BB), 384>>>(alog, Dp);
    k_rmsgate<<<ROWS, 128>>>(nw);
    k_outproj_mma<<<dim3(DMD/128, (BB*LL)/128, MMOD), 256>>>(scl, out);
}